// round 17
// baseline (speedup 1.0000x reference)
#include <cuda_runtime.h>
#include <cuda_bf16.h>
#include <cstdint>

// Problem constants
#define BATCH 64
#define SEQ   512
#define EMB   256
#define DOUT  512
#define KBIG  1536          // 6 combined taps * EMB
#define KFIX  768           // 3 taps of x used by edge corrections
#define SEQP  (SEQ + 2)     // X padded with 2 zero rows at front (per batch)

// ---------------- device scratch (static globals: allowed) ----------------
__device__ __nv_bfloat16 g_Xh[BATCH * SEQP * EMB];   // bf16 hi of padded X
__device__ __nv_bfloat16 g_Xl[BATCH * SEQP * EMB];   // bf16 lo of padded X
// Repacked combined weights: g_WbR*[ (e16_group*512 + d) * 96 + t*16 + j ]
//   = Wb[d][ t*256 + e16_group*16 + j ]   (chunk-contiguous: 96 elems/row)
__device__ __nv_bfloat16 g_WbRh[DOUT * KBIG];
__device__ __nv_bfloat16 g_WbRl[DOUT * KBIG];
// Repacked unigram weights: g_W1R*[ (e16_group*512 + d) * 16 + j ]
__device__ __nv_bfloat16 g_W1Rh[DOUT * EMB];
__device__ __nv_bfloat16 g_W1Rl[DOUT * EMB];
__device__ float g_bias[DOUT];
__device__ float g_Wfix0[DOUT * KFIX];
__device__ float g_Wfix1[DOUT * KFIX];
__device__ float g_bfix0[DOUT];
__device__ float g_bfix1[DOUT];
__device__ float g_corr[BATCH * 2 * DOUT];           // edge corrections (i=0,1)

// ---------------- baseline-PTX helpers (no sm_103a-only features) ---------
__device__ __forceinline__ uint32_t smem_u32(const void* p) {
    uint32_t a;
    asm("{ .reg .u64 t; cvta.to.shared.u64 t, %1; cvt.u32.u64 %0, t; }"
        : "=r"(a) : "l"(p));
    return a;
}

#define CPASYNC16(dst, src) \
    asm volatile("cp.async.cg.shared.global [%0], [%1], 16;" \
                 :: "r"((uint32_t)(dst)), "l"(src) : "memory")
#define CP_COMMIT()  asm volatile("cp.async.commit_group;" ::: "memory")
#define CP_WAIT(n)   asm volatile("cp.async.wait_group %0;" :: "n"(n) : "memory")

#define LDSM4(r, addr) \
    asm volatile("ldmatrix.sync.aligned.m8n8.x4.shared.b16 {%0,%1,%2,%3}, [%4];" \
        : "=r"((r)[0]), "=r"((r)[1]), "=r"((r)[2]), "=r"((r)[3]) \
        : "r"((uint32_t)(addr)))

#define MMA_BF16(c, a, b0, b1) \
    asm volatile("mma.sync.aligned.m16n8k16.row.col.f32.bf16.bf16.f32 " \
        "{%0,%1,%2,%3}, {%4,%5,%6,%7}, {%8,%9}, {%0,%1,%2,%3};" \
        : "+f"((c)[0]), "+f"((c)[1]), "+f"((c)[2]), "+f"((c)[3]) \
        : "r"((a)[0]), "r"((a)[1]), "r"((a)[2]), "r"((a)[3]), \
          "r"(b0), "r"(b1))

__device__ __forceinline__ void bsplit(float v, __nv_bfloat16& h, __nv_bfloat16& l) {
    h = __float2bfloat16(v);
    l = __float2bfloat16(v - __bfloat162float(h));
}

// ---------------------------------------------------------------------------
// Fold the 4 conv branches + window sums into a 6-tap combined conv weight
// (bf16 hi/lo split, repacked chunk-contiguous), plus edge-correction rows.
// Steady-state (i in [2,255]) tap combinations:
//   t=-2: W4[0]
//   t=-1: W3[0] + W4[0]+W4[1]
//   t= 0: W1 + W2[0] + W3[0]+W3[1] + W4[0]+W4[1]+W4[2]
//   t=+1: W2[1] + W3[1]+W3[2] + W4[1]+W4[2]+W4[3]
//   t=+2: W3[2] + W4[2]+W4[3]
//   t=+3: W4[3]
// bias_s = b1 + b2 + 2*b3 + 3*b4
// ---------------------------------------------------------------------------
__global__ void combine_weights_kernel(
    const float* __restrict__ W1, const float* __restrict__ b1,
    const float* __restrict__ W2, const float* __restrict__ b2,
    const float* __restrict__ W3, const float* __restrict__ b3,
    const float* __restrict__ W4, const float* __restrict__ b4)
{
    int idx = blockIdx.x * blockDim.x + threadIdx.x;
    if (idx >= DOUT * EMB) return;
    int d = idx / EMB, e = idx % EMB;
    int eg = e >> 4, ej = e & 15;

    float w1  = W1[d * EMB + e];
    const float* w2 = W2 + (size_t)(d * EMB + e) * 2;
    const float* w3 = W3 + (size_t)(d * EMB + e) * 3;
    const float* w4 = W4 + (size_t)(d * EMB + e) * 4;
    float w20 = w2[0], w21 = w2[1];
    float w30 = w3[0], w31 = w3[1], w32 = w3[2];
    float w40 = w4[0], w41 = w4[1], w42 = w4[2], w43 = w4[3];

    float taps[6];
    taps[0] = w40;
    taps[1] = w30 + w40 + w41;
    taps[2] = w1 + w20 + w30 + w31 + w40 + w41 + w42;
    taps[3] = w21 + w31 + w32 + w41 + w42 + w43;
    taps[4] = w32 + w42 + w43;
    taps[5] = w43;
    size_t rbase = ((size_t)(eg * 512 + d)) * 96 + ej;
#pragma unroll
    for (int t = 0; t < 6; t++) {
        __nv_bfloat16 h, l;
        bsplit(taps[t], h, l);
        g_WbRh[rbase + t * 16] = h;
        g_WbRl[rbase + t * 16] = l;
    }
    {
        __nv_bfloat16 h, l;
        bsplit(w1, h, l);
        size_t r1 = ((size_t)(eg * 512 + d)) * 16 + ej;
        g_W1Rh[r1] = h;
        g_W1Rl[r1] = l;
    }

    float* f0 = g_Wfix0 + (size_t)d * KFIX;
    float* f1 = g_Wfix1 + (size_t)d * KFIX;
    f0[0 * EMB + e] = w31 + w41 + w42;
    f0[1 * EMB + e] = w32 + w42 + w43;
    f0[2 * EMB + e] = w43;
    f1[0 * EMB + e] = w41;
    f1[1 * EMB + e] = w42;
    f1[2 * EMB + e] = w43;

    if (e == 0) {
        g_bias[d]  = b1[d] + b2[d] + 2.0f * b3[d] + 3.0f * b4[d];
        g_bfix0[d] = b3[d] + 2.0f * b4[d];
        g_bfix1[d] = b4[d];
    }
}

// ---------------------------------------------------------------------------
// Fused prep kernel (single launch, independent block groups):
//  blocks [0, CVT_BLOCKS): convert X into padded bf16 hi/lo arrays.
//  blocks [CVT_BLOCKS, +512): compute edge corrections g_corr (i=0,1).
// ---------------------------------------------------------------------------
#define CVT_BLOCKS (BATCH * SEQP * EMB / 4 / 256)   // 8224 (exact)

__global__ void __launch_bounds__(256) prep_kernel(const float* __restrict__ X)
{
    __shared__ float sx[8][KFIX];
    const int tid = threadIdx.x;

    if (blockIdx.x < CVT_BLOCKS) {
        int u = blockIdx.x * 256 + tid;          // one float4 unit
        int e4  = u & 63;
        int row = u >> 6;            // b*SEQP + r
        int r   = row % SEQP;
        __nv_bfloat16 h[4], l[4];
        if (r < 2) {
#pragma unroll
            for (int j = 0; j < 4; j++) { h[j] = __float2bfloat16(0.f); l[j] = h[j]; }
        } else {
            int b = row / SEQP;
            float4 v = *reinterpret_cast<const float4*>(
                X + ((size_t)(b * SEQ + (r - 2))) * EMB + e4 * 4);
            float a[4] = {v.x, v.y, v.z, v.w};
#pragma unroll
            for (int j = 0; j < 4; j++) bsplit(a[j], h[j], l[j]);
        }
        size_t o = (size_t)row * EMB + e4 * 4;
        *reinterpret_cast<__nv_bfloat162*>(g_Xh + o)     = __halves2bfloat162(h[0], h[1]);
        *reinterpret_cast<__nv_bfloat162*>(g_Xh + o + 2) = __halves2bfloat162(h[2], h[3]);
        *reinterpret_cast<__nv_bfloat162*>(g_Xl + o)     = __halves2bfloat162(l[0], l[1]);
        *reinterpret_cast<__nv_bfloat162*>(g_Xl + o + 2) = __halves2bfloat162(l[2], l[3]);
        return;
    }

    int cb = blockIdx.x - CVT_BLOCKS;            // 0..511
    int b0 = (cb & 7) * 8;
    int d  = (cb >> 3) * 8 + (tid >> 5);
    int lane = tid & 31;

    for (int u = tid; u < 8 * KFIX; u += 256) {
        int bb = u / KFIX, k = u % KFIX;
        sx[bb][k] = X[(size_t)(b0 + bb) * SEQ * EMB + k];
    }
    __syncthreads();

    const float* w0 = g_Wfix0 + (size_t)d * KFIX;
    const float* w1 = g_Wfix1 + (size_t)d * KFIX;
    float a0[8], a1[8];
#pragma unroll
    for (int bb = 0; bb < 8; bb++) { a0[bb] = 0.0f; a1[bb] = 0.0f; }

#pragma unroll 4
    for (int t = 0; t < KFIX / 32; t++) {
        int k = lane + 32 * t;
        float v0 = w0[k], v1 = w1[k];
#pragma unroll
        for (int bb = 0; bb < 8; bb++) {
            float xv = sx[bb][k];
            a0[bb] = fmaf(xv, v0, a0[bb]);
            a1[bb] = fmaf(xv, v1, a1[bb]);
        }
    }
#pragma unroll
    for (int off = 16; off; off >>= 1) {
#pragma unroll
        for (int bb = 0; bb < 8; bb++) {
            a0[bb] += __shfl_xor_sync(0xFFFFFFFFu, a0[bb], off);
            a1[bb] += __shfl_xor_sync(0xFFFFFFFFu, a1[bb], off);
        }
    }
    if (lane == 0) {
        float c0 = g_bfix0[d], c1 = g_bfix1[d];
#pragma unroll
        for (int bb = 0; bb < 8; bb++) {
            g_corr[(size_t)((b0 + bb) * 2 + 0) * DOUT + d] = a0[bb] + c0;
            g_corr[(size_t)((b0 + bb) * 2 + 1) * DOUT + d] = a1[bb] + c1;
        }
    }
}

// ---------------------------------------------------------------------------
// Sliding-window HMMA GEMM.  CTA tile 256(M=one batch) x 128(N), 512 threads
// (16 warps, 8(m) x 2(n), warp tile 32x64).  The main region exploits the
// sliding-window structure of A: smem holds a 261-row x 16-elem window of
// padded x; tap t's A tile is the window shifted by t rows (ldmatrix base +
// t*AROWB).  B is pre-repacked chunk-contiguous (96 elems per n-row per
// e16-group).  K loop = 16 e16-groups, each spanning all taps.
// 2-stage cp.async ring, strides 48B (A) / 208B (B): conflict-free ldmatrix.
// bid<256: main (K=1536, taps=6);  bid>=256: tail (K=256, taps=1, unigram).
// ---------------------------------------------------------------------------
#define AROWB 48
#define BROWB 208
#define A_REG (264 * AROWB)                    // 12672
#define OFF_AH 0
#define OFF_AL A_REG
#define OFF_BH (2 * A_REG)                     // 25344
#define OFF_BL (2 * A_REG + 128 * BROWB)       // 51968
#define STG_BYTES (2 * A_REG + 2 * 128 * BROWB)  // 78592
#define SMEM_TOTAL (2 * STG_BYTES)             // 157184

template<int TAPS>
__device__ __forceinline__ void chunk_mma(
    uint32_t sb, uint32_t aRowOff, uint32_t bRowOff, float acc[2][8][4])
{
#pragma unroll
    for (int t = 0; t < TAPS; t++) {
        uint32_t ah[2][4], al[2][4];
        uint32_t ra = aRowOff + t * AROWB;
        LDSM4(ah[0], sb + OFF_AH + ra);
        LDSM4(ah[1], sb + OFF_AH + ra + 16 * AROWB);
        LDSM4(al[0], sb + OFF_AL + ra);
        LDSM4(al[1], sb + OFF_AL + ra + 16 * AROWB);
        uint32_t kOff = t * 32;
#pragma unroll
        for (int p = 0; p < 4; p++) {
            uint32_t rb = bRowOff + p * 16 * BROWB + kOff;
            uint32_t bh[4], bl[4];
            LDSM4(bh, sb + OFF_BH + rb);
            LDSM4(bl, sb + OFF_BL + rb);
#pragma unroll
            for (int mt = 0; mt < 2; mt++) {
                MMA_BF16(acc[mt][2 * p],     ah[mt], bh[0], bh[1]);
                MMA_BF16(acc[mt][2 * p],     ah[mt], bl[0], bl[1]);
                MMA_BF16(acc[mt][2 * p],     al[mt], bh[0], bh[1]);
                MMA_BF16(acc[mt][2 * p + 1], ah[mt], bh[2], bh[3]);
                MMA_BF16(acc[mt][2 * p + 1], ah[mt], bl[2], bl[3]);
                MMA_BF16(acc[mt][2 * p + 1], al[mt], bh[2], bh[3]);
            }
        }
    }
}

__global__ void __launch_bounds__(512, 1) gemm_tc_kernel(
    const float* __restrict__ b1, float* __restrict__ out)
{
    extern __shared__ char smem[];
    const uint32_t sbase = smem_u32(smem);
    const int tid = threadIdx.x;
    const int lane = tid & 31, wid = tid >> 5;
    const int wm = wid & 7, wn = wid >> 3;     // 8(m) x 2(n) warp grid

    const int bid   = blockIdx.x;
    const int mode  = bid >> 8;                // 0 = main, 1 = tail
    const int local = bid & 255;
    const int n0    = (local & 3) * 128;
    const int btile = local >> 2;              // 0..63 = batch
    const int maxr  = mode ? 255 : 260;        // last valid window row
    const size_t xbase =
        ((size_t)(btile * SEQP + (mode ? 258 : 0))) * EMB;

    // ---- ldmatrix lane addressing ----
    const uint32_t aRowOff = (uint32_t)((wm * 32 + (lane & 15)) * AROWB)
                           + (uint32_t)((lane >> 4) * 16);
    const uint32_t bRowOff = (uint32_t)((wn * 64 + (lane & 7) +
                                         ((lane & 16) ? 8 : 0)) * BROWB)
                           + (uint32_t)((lane & 8) ? 16 : 0);

    float acc[2][8][4];
#pragma unroll
    for (int mt = 0; mt < 2; mt++)
#pragma unroll
        for (int g = 0; g < 8; g++)
#pragma unroll
            for (int c = 0; c < 4; c++) acc[mt][g][c] = 0.0f;

    // ---- stage filler: e = e16-group index (0..15) ----
    auto load_stage = [&](int e, int st) {
        uint32_t sb = sbase + st * STG_BYTES;
        // A window: 264 rows x 32B (hi + lo); rows past maxr clamp (dup, unused)
        for (int tau = tid; tau < 528; tau += 512) {
            int row = tau >> 1, half = tau & 1;
            int rc = row > maxr ? maxr : row;
            size_t src = xbase + (size_t)rc * EMB + e * 16 + half * 8;
            uint32_t dst = (uint32_t)(row * AROWB + half * 16);
            CPASYNC16(sb + OFF_AH + dst, g_Xh + src);
            CPASYNC16(sb + OFF_AL + dst, g_Xl + src);
        }
        if (mode == 0) {
            // B: 128 rows x 192B (12 x 16B segs), hi + lo
            for (int tau = tid; tau < 1536; tau += 512) {
                int row = tau & 127, seg = tau >> 7;
                size_t src = ((size_t)(e * 512 + n0 + row)) * 96 + seg * 8;
                uint32_t dst = (uint32_t)(row * BROWB + seg * 16);
                CPASYNC16(sb + OFF_BH + dst, g_WbRh + src);
                CPASYNC16(sb + OFF_BL + dst, g_WbRl + src);
            }
        } else {
            // B: 128 rows x 32B (2 x 16B), hi + lo
            if (tid < 256) {
                int row = tid >> 1, half = tid & 1;
                size_t src = ((size_t)(e * 512 + n0 + row)) * 16 + half * 8;
                uint32_t dst = (uint32_t)(row * BROWB + half * 16);
                CPASYNC16(sb + OFF_BH + dst, g_W1Rh + src);
                CPASYNC16(sb + OFF_BL + dst, g_W1Rl + src);
            }
        }
        CP_COMMIT();
    };

    load_stage(0, 0);   // prologue

    for (int kt = 0; kt < 16; kt++) {
        if (kt + 1 < 16) {
            load_stage(kt + 1, (kt + 1) & 1);
            CP_WAIT(1);
        } else {
            CP_WAIT(0);
        }
        __syncthreads();

        uint32_t sb = sbase + (kt & 1) * STG_BYTES;
        if (mode == 0) chunk_mma<6>(sb, aRowOff, bRowOff, acc);
        else           chunk_mma<1>(sb, aRowOff, bRowOff, acc);
        __syncthreads();   // all reads done before this buffer is refilled
    }

    // ---- epilogue: add bias, subtract edge corr (i<2), store fp32 ----
    const float* bias = mode ? b1 : g_bias;
    const int nbase = n0 + wn * 64 + (lane & 3) * 2;
    float bv[8][2];
#pragma unroll
    for (int g = 0; g < 8; g++) {
        bv[g][0] = bias[nbase + g * 8];
        bv[g][1] = bias[nbase + g * 8 + 1];
    }
    const int mloc = wm * 32 + (lane >> 2);
#pragma unroll
    for (int mt = 0; mt < 2; mt++) {
        int i = mloc + mt * 16 + (mode ? 256 : 0);
        float* o0 = out + ((size_t)(btile * SEQ + i)) * DOUT + nbase;
        float* o1 = o0 + 8 * DOUT;   // row i+8 (same batch)
        const bool fix = (mode == 0) && (i < 2);
        const float* cr = g_corr + (size_t)(btile * 2 + i) * DOUT + nbase;
#pragma unroll
        for (int g = 0; g < 8; g++) {
            float2 v0, v1;
            v0.x = acc[mt][g][0] + bv[g][0];
            v0.y = acc[mt][g][1] + bv[g][1];
            v1.x = acc[mt][g][2] + bv[g][0];
            v1.y = acc[mt][g][3] + bv[g][1];
            if (fix) {
                v0.x -= cr[g * 8];
                v0.y -= cr[g * 8 + 1];
            }
            *reinterpret_cast<float2*>(o0 + g * 8) = v0;
            *reinterpret_cast<float2*>(o1 + g * 8) = v1;
        }
    }
}

// ---------------------------------------------------------------------------
extern "C" void kernel_launch(void* const* d_in, const int* in_sizes, int n_in,
                              void* d_out, int out_size)
{
    const float* X  = (const float*)d_in[0];
    const float* W1 = (const float*)d_in[1];
    const float* b1 = (const float*)d_in[2];
    const float* W2 = (const float*)d_in[3];
    const float* b2 = (const float*)d_in[4];
    const float* W3 = (const float*)d_in[5];
    const float* b3 = (const float*)d_in[6];
    const float* W4 = (const float*)d_in[7];
    const float* b4 = (const float*)d_in[8];
    float* out = (float*)d_out;

    cudaFuncSetAttribute(gemm_tc_kernel,
                         cudaFuncAttributeMaxDynamicSharedMemorySize, SMEM_TOTAL);

    // 1. Fold branches + window sums into repacked bf16 hi/lo weights + Wfix
    combine_weights_kernel<<<(DOUT * EMB + 255) / 256, 256>>>(
        W1, b1, W2, b2, W3, b3, W4, b4);

    // 2. Fused: split X into padded bf16 hi/lo  +  compute edge corrections
    prep_kernel<<<CVT_BLOCKS + 512, 256>>>(X);

    // 3. Sliding-window HMMA GEMM: main (bid<256) then tail (bid>=256)
    gemm_tc_kernel<<<512, 512, SMEM_TOTAL>>>(b1, out);
}